// round 2
// baseline (speedup 1.0000x reference)
#include <cuda_runtime.h>
#include <math.h>
#include <stdint.h>

// ---------------- problem constants ----------------
#define BATCH 2
#define SEQ   1024
#define T     2048            // BATCH*SEQ tokens
#define DMODEL 1024
#define NHEAD 16
#define NKV   4
#define HDIM  64
#define NLAYER 4
#define NEXP  8
#define FDIM  1024
#define VOCAB 32000
#define MOE_ROWS (2*T + 64)   // padded for unguarded tile loads

// ---------------- scratch (device globals; no allocs allowed) ----------------
__device__ float g_x [T*DMODEL];
__device__ float g_h [T*DMODEL];
__device__ float g_q [T*NHEAD*HDIM];
__device__ float g_k [T*NKV*HDIM];
__device__ float g_v [T*NKV*HDIM];
__device__ float g_ao[T*NHEAD*HDIM];
__device__ int   g_topi[T*2];
__device__ float g_gate[T*2];
__device__ int   g_cnt[NEXP];
__device__ int   g_off[NEXP+1];
__device__ int   g_cur[NEXP];
__device__ int   g_ptok[T*2];
__device__ int   g_rowof[T*2];
__device__ float g_hg[(size_t)MOE_ROWS*DMODEL];
__device__ float g_gb[(size_t)MOE_ROWS*FDIM];
__device__ float g_ub[(size_t)MOE_ROWS*FDIM];
__device__ float g_yb[(size_t)MOE_ROWS*DMODEL];

// ---------------- embed ----------------
__global__ void embed_k(const int* __restrict__ ids, const float* __restrict__ emb) {
    int t = blockIdx.x;
    int id = ids[t];
    for (int d = threadIdx.x; d < DMODEL; d += 256)
        g_x[(size_t)t*DMODEL + d] = emb[(size_t)id*DMODEL + d];
}

// ---------------- rmsnorm over DMODEL ----------------
__global__ void rmsnorm_k(const float* __restrict__ in, const float* __restrict__ w,
                          float* __restrict__ out) {
    int t = blockIdx.x, tid = threadIdx.x;
    __shared__ float red[256];
    float s = 0.f;
    for (int d = tid; d < DMODEL; d += 256) { float v = in[(size_t)t*DMODEL + d]; s += v*v; }
    red[tid] = s; __syncthreads();
    for (int off = 128; off > 0; off >>= 1) { if (tid < off) red[tid] += red[tid+off]; __syncthreads(); }
    float r = rsqrtf(red[0]/(float)DMODEL + 1e-6f);
    for (int d = tid; d < DMODEL; d += 256)
        out[(size_t)t*DMODEL + d] = in[(size_t)t*DMODEL + d] * r * w[d];
}

// ---------------- generic tiled SGEMM: C = A[MxK] @ B[KxN] (+ optional residual) ----------------
#define BM 64
#define BN 64
#define BK 16
__global__ void sgemm_nn(const float* __restrict__ A, const float* __restrict__ B,
                         float* __restrict__ C, const float* __restrict__ Crs,
                         int M, int N, int K) {
    __shared__ float As[BK][BM+1];
    __shared__ float Bs[BK][BN+1];
    const int n0 = blockIdx.x*BN, m0 = blockIdx.y*BM;
    const int tid = threadIdx.x;
    const int tx = tid & 15, ty = tid >> 4;
    float acc[4][4] = {};
    for (int k0 = 0; k0 < K; k0 += BK) {
#pragma unroll
        for (int i = 0; i < 4; i++) {
            int idx = tid + i*256;
            int m = idx >> 4, kk = idx & 15;
            As[kk][m] = A[(size_t)(m0+m)*K + k0 + kk];
        }
#pragma unroll
        for (int i = 0; i < 4; i++) {
            int idx = tid + i*256;
            int kk = idx >> 6, n = idx & 63;
            Bs[kk][n] = B[(size_t)(k0+kk)*N + n0 + n];
        }
        __syncthreads();
#pragma unroll
        for (int kk = 0; kk < BK; kk++) {
            float a[4], b[4];
#pragma unroll
            for (int i = 0; i < 4; i++) a[i] = As[kk][ty*4+i];
#pragma unroll
            for (int j = 0; j < 4; j++) b[j] = Bs[kk][tx*4+j];
#pragma unroll
            for (int i = 0; i < 4; i++)
#pragma unroll
                for (int j = 0; j < 4; j++) acc[i][j] += a[i]*b[j];
        }
        __syncthreads();
    }
#pragma unroll
    for (int i = 0; i < 4; i++) {
        int row = m0 + ty*4 + i;
#pragma unroll
        for (int j = 0; j < 4; j++) {
            int col = n0 + tx*4 + j;
            float v = acc[i][j];
            if (Crs) v += Crs[(size_t)row*N + col];
            C[(size_t)row*N + col] = v;
        }
    }
}

// B transposed variant: C = A[MxK] @ Bt^T, Bt is [N, K] row-major (lm_head, tied emb)
__global__ void sgemm_nt(const float* __restrict__ A, const float* __restrict__ Bt,
                         float* __restrict__ C, int M, int N, int K) {
    __shared__ float As[BK][BM+1];
    __shared__ float Bs[BK][BN+1];
    const int n0 = blockIdx.x*BN, m0 = blockIdx.y*BM;
    const int tid = threadIdx.x;
    const int tx = tid & 15, ty = tid >> 4;
    float acc[4][4] = {};
    for (int k0 = 0; k0 < K; k0 += BK) {
#pragma unroll
        for (int i = 0; i < 4; i++) {
            int idx = tid + i*256;
            int m = idx >> 4, kk = idx & 15;
            As[kk][m] = A[(size_t)(m0+m)*K + k0 + kk];
        }
#pragma unroll
        for (int i = 0; i < 4; i++) {
            int idx = tid + i*256;
            int kk = idx & 15, n = idx >> 4;
            Bs[kk][n] = Bt[(size_t)(n0+n)*K + k0 + kk];
        }
        __syncthreads();
#pragma unroll
        for (int kk = 0; kk < BK; kk++) {
            float a[4], b[4];
#pragma unroll
            for (int i = 0; i < 4; i++) a[i] = As[kk][ty*4+i];
#pragma unroll
            for (int j = 0; j < 4; j++) b[j] = Bs[kk][tx*4+j];
#pragma unroll
            for (int i = 0; i < 4; i++)
#pragma unroll
                for (int j = 0; j < 4; j++) acc[i][j] += a[i]*b[j];
        }
        __syncthreads();
    }
#pragma unroll
    for (int i = 0; i < 4; i++) {
        int row = m0 + ty*4 + i;
#pragma unroll
        for (int j = 0; j < 4; j++)
            C[(size_t)row*N + n0 + tx*4 + j] = acc[i][j];
    }
}

// Per-expert grouped GEMM over gathered rows. A=[MOE_ROWS,K] abs-indexed, Ball=[E,K,N]
__global__ void sgemm_moe(const float* __restrict__ A, const float* __restrict__ Ball,
                          float* __restrict__ C, int N, int K) {
    const int e = blockIdx.z;
    const int r0 = g_off[e], r1 = g_off[e+1];
    const int m0 = r0 + blockIdx.y*BM;
    if (m0 >= r1) return;
    const float* B = Ball + (size_t)e*K*N;
    __shared__ float As[BK][BM+1];
    __shared__ float Bs[BK][BN+1];
    const int n0 = blockIdx.x*BN;
    const int tid = threadIdx.x;
    const int tx = tid & 15, ty = tid >> 4;
    float acc[4][4] = {};
    for (int k0 = 0; k0 < K; k0 += BK) {
#pragma unroll
        for (int i = 0; i < 4; i++) {
            int idx = tid + i*256;
            int m = idx >> 4, kk = idx & 15;
            As[kk][m] = A[(size_t)(m0+m)*K + k0 + kk];   // padded buffer: safe
        }
#pragma unroll
        for (int i = 0; i < 4; i++) {
            int idx = tid + i*256;
            int kk = idx >> 6, n = idx & 63;
            Bs[kk][n] = B[(size_t)(k0+kk)*N + n0 + n];
        }
        __syncthreads();
#pragma unroll
        for (int kk = 0; kk < BK; kk++) {
            float a[4], b[4];
#pragma unroll
            for (int i = 0; i < 4; i++) a[i] = As[kk][ty*4+i];
#pragma unroll
            for (int j = 0; j < 4; j++) b[j] = Bs[kk][tx*4+j];
#pragma unroll
            for (int i = 0; i < 4; i++)
#pragma unroll
                for (int j = 0; j < 4; j++) acc[i][j] += a[i]*b[j];
        }
        __syncthreads();
    }
#pragma unroll
    for (int i = 0; i < 4; i++) {
        int row = m0 + ty*4 + i;
        if (row < r1) {
#pragma unroll
            for (int j = 0; j < 4; j++)
                C[(size_t)row*N + n0 + tx*4 + j] = acc[i][j];
        }
    }
}

// ---------------- per-head rmsnorm + RoPE (q: nh=16 block=1024, k: nh=4 block=256) ----------------
__global__ void qknorm_rope_k(float* __restrict__ x, const float* __restrict__ w,
                              const int* __restrict__ pos, int nh) {
    int t = blockIdx.x, tid = threadIdx.x;
    int hh = tid >> 6, d = tid & 63;
    __shared__ float sh[NHEAD*HDIM];
    float v = x[(size_t)t*nh*HDIM + tid];
    sh[tid] = v*v; __syncthreads();
    for (int off = 32; off > 0; off >>= 1) { if (d < off) sh[tid] += sh[tid+off]; __syncthreads(); }
    float r = rsqrtf(sh[hh*64]/64.0f + 1e-6f);
    __syncthreads();
    float nv = v * r * w[d];
    sh[tid] = nv; __syncthreads();
    float other = (d < 32) ? -sh[hh*64 + d + 32] : sh[hh*64 + d - 32];
    int i = d & 31;
    double invf = exp(-((double)i/32.0) * 13.815510557964274);  // ln(1e6)
    float ang = (float)((double)pos[t] * invf);
    float sv, cv;
    sincosf(ang, &sv, &cv);
    x[(size_t)t*nh*HDIM + tid] = nv*cv + other*sv;
}

// ---------------- attention: one block per (qpos, head, batch) ----------------
__global__ void attn_k() {
    const int qpos = blockIdx.x, h = blockIdx.y, b = blockIdx.z;
    const int tid = threadIdx.x;
    const int kvh = h >> 2;                 // GQA: 4 q-heads per kv head
    const int t = b*SEQ + qpos;
    __shared__ float qv[HDIM];
    __shared__ float sc[SEQ];
    __shared__ float red[128];
    if (tid < HDIM) qv[tid] = g_q[(size_t)t*(NHEAD*HDIM) + h*HDIM + tid];
    __syncthreads();
    const int nk = qpos + 1;
    float lm = -1e30f;
    for (int j = tid; j < nk; j += 128) {
        const float* kp = g_k + ((size_t)(b*SEQ + j)*NKV + kvh)*HDIM;
        float s = 0.f;
#pragma unroll
        for (int dd = 0; dd < HDIM; dd++) s += qv[dd]*kp[dd];
        s *= 0.125f;                        // 1/sqrt(64)
        sc[j] = s;
        lm = fmaxf(lm, s);
    }
    red[tid] = lm; __syncthreads();
    for (int off = 64; off > 0; off >>= 1) { if (tid < off) red[tid] = fmaxf(red[tid], red[tid+off]); __syncthreads(); }
    float m = red[0]; __syncthreads();
    float ls = 0.f;
    for (int j = tid; j < nk; j += 128) { float p = __expf(sc[j] - m); sc[j] = p; ls += p; }
    red[tid] = ls; __syncthreads();
    for (int off = 64; off > 0; off >>= 1) { if (tid < off) red[tid] += red[tid+off]; __syncthreads(); }
    float inv = 1.0f / red[0];
    if (tid < HDIM) {
        float acc = 0.f;
        for (int j = 0; j < nk; j++)
            acc += sc[j] * g_v[((size_t)(b*SEQ + j)*NKV + kvh)*HDIM + tid];
        g_ao[(size_t)t*(NHEAD*HDIM) + h*HDIM + tid] = acc * inv;
    }
}

// ---------------- router: logits, softmax, top-2, normalized gates ----------------
__global__ void router_k(const float* __restrict__ rw) {
    int t = blockIdx.x, tid = threadIdx.x;
    float acc[NEXP] = {};
    for (int d = tid; d < DMODEL; d += 256) {
        float hv = g_h[(size_t)t*DMODEL + d];
        const float* rp = rw + (size_t)d*NEXP;
#pragma unroll
        for (int e = 0; e < NEXP; e++) acc[e] += hv*rp[e];
    }
    __shared__ float red[256];
    __shared__ float logits[NEXP];
    for (int e = 0; e < NEXP; e++) {
        red[tid] = acc[e]; __syncthreads();
        for (int off = 128; off > 0; off >>= 1) { if (tid < off) red[tid] += red[tid+off]; __syncthreads(); }
        if (tid == 0) logits[e] = red[0];
        __syncthreads();
    }
    if (tid == 0) {
        float mx = logits[0];
        for (int e = 1; e < NEXP; e++) mx = fmaxf(mx, logits[e]);
        float p[NEXP];
        for (int e = 0; e < NEXP; e++) p[e] = expf(logits[e] - mx);
        int i0 = 0;
        for (int e = 1; e < NEXP; e++) if (p[e] > p[i0]) i0 = e;   // ties -> lowest idx, matches top_k
        int i1 = (i0 == 0) ? 1 : 0;
        for (int e = 0; e < NEXP; e++) if (e != i0 && p[e] > p[i1]) i1 = e;
        float v0 = p[i0], v1 = p[i1], tt = v0 + v1;
        g_topi[t*2] = i0;  g_topi[t*2+1] = i1;
        g_gate[t*2] = v0/tt; g_gate[t*2+1] = v1/tt;   // softmax denom cancels in topv/sum(topv)
    }
}

// ---------------- routing bookkeeping ----------------
__global__ void route_zero_k()   { if (threadIdx.x < NEXP) g_cnt[threadIdx.x] = 0; }
__global__ void route_count_k()  { int i = blockIdx.x*256 + threadIdx.x; if (i < 2*T) atomicAdd(&g_cnt[g_topi[i]], 1); }
__global__ void route_prefix_k() {
    if (threadIdx.x == 0) {
        int s = 0;
        for (int e = 0; e < NEXP; e++) { g_off[e] = s; g_cur[e] = s; s += g_cnt[e]; }
        g_off[NEXP] = s;
    }
}
__global__ void route_assign_k() {
    int i = blockIdx.x*256 + threadIdx.x;
    if (i < 2*T) {
        int e = g_topi[i];
        int pos = atomicAdd(&g_cur[e], 1);
        g_ptok[pos] = i >> 1;
        g_rowof[i] = pos;
    }
}
__global__ void moe_gather_k() {
    int i = blockIdx.x;
    int tk = g_ptok[i];
    for (int d = threadIdx.x; d < DMODEL; d += 256)
        g_hg[(size_t)i*DMODEL + d] = g_h[(size_t)tk*DMODEL + d];
}
__global__ void moe_act_k() {
    size_t i = (size_t)blockIdx.x*256 + threadIdx.x;   // grid covers 2*T*FDIM
    float g = g_gb[i], u = g_ub[i];
    float sg = g / (1.0f + expf(-g));
    g_gb[i] = sg * u;
}
__global__ void moe_combine_k() {
    int t = blockIdx.x;
    int r0 = g_rowof[t*2], r1 = g_rowof[t*2+1];
    float w0 = g_gate[t*2], w1 = g_gate[t*2+1];
    for (int d = threadIdx.x; d < DMODEL; d += 256)
        g_x[(size_t)t*DMODEL + d] += w0*g_yb[(size_t)r0*DMODEL + d]
                                   + w1*g_yb[(size_t)r1*DMODEL + d];
}

// ---------------- host orchestration ----------------
extern "C" void kernel_launch(void* const* d_in, const int* in_sizes, int n_in,
                              void* d_out, int out_size) {
    const int*   token_ids    = (const int*)  d_in[0];
    const int*   position_ids = (const int*)  d_in[1];
    const float* tok_emb      = (const float*)d_in[2];
    const float* attn_norm_w  = (const float*)d_in[3];
    const float* wq           = (const float*)d_in[4];
    const float* wk           = (const float*)d_in[5];
    const float* wv           = (const float*)d_in[6];
    const float* q_norm_w     = (const float*)d_in[7];
    const float* k_norm_w     = (const float*)d_in[8];
    const float* wo           = (const float*)d_in[9];
    const float* ffn_norm_w   = (const float*)d_in[10];
    const float* router_w     = (const float*)d_in[11];
    const float* gate_w       = (const float*)d_in[12];
    const float* up_w         = (const float*)d_in[13];
    const float* down_w       = (const float*)d_in[14];
    const float* final_norm_w = (const float*)d_in[15];
    float* out = (float*)d_out;

    float* px; cudaGetSymbolAddress((void**)&px, g_x);
    float* ph; cudaGetSymbolAddress((void**)&ph, g_h);
    float* pq; cudaGetSymbolAddress((void**)&pq, g_q);
    float* pk; cudaGetSymbolAddress((void**)&pk, g_k);
    float* pv; cudaGetSymbolAddress((void**)&pv, g_v);
    float* pao; cudaGetSymbolAddress((void**)&pao, g_ao);
    float* phg; cudaGetSymbolAddress((void**)&phg, g_hg);
    float* pgb; cudaGetSymbolAddress((void**)&pgb, g_gb);
    float* pub; cudaGetSymbolAddress((void**)&pub, g_ub);
    float* pyb; cudaGetSymbolAddress((void**)&pyb, g_yb);

    embed_k<<<T, 256>>>(token_ids, tok_emb);

    for (int l = 0; l < NLAYER; l++) {
        const float* wq_l = wq + (size_t)l*DMODEL*(NHEAD*HDIM);
        const float* wk_l = wk + (size_t)l*DMODEL*(NKV*HDIM);
        const float* wv_l = wv + (size_t)l*DMODEL*(NKV*HDIM);
        const float* wo_l = wo + (size_t)l*(NHEAD*HDIM)*DMODEL;
        const float* gw_l = gate_w + (size_t)l*NEXP*DMODEL*FDIM;
        const float* uw_l = up_w   + (size_t)l*NEXP*DMODEL*FDIM;
        const float* dw_l = down_w + (size_t)l*NEXP*FDIM*DMODEL;

        // attention block
        rmsnorm_k<<<T, 256>>>(px, attn_norm_w + (size_t)l*DMODEL, ph);
        sgemm_nn<<<dim3((NHEAD*HDIM)/BN, T/BM), 256>>>(ph, wq_l, pq, nullptr, T, NHEAD*HDIM, DMODEL);
        sgemm_nn<<<dim3((NKV*HDIM)/BN,  T/BM), 256>>>(ph, wk_l, pk, nullptr, T, NKV*HDIM, DMODEL);
        sgemm_nn<<<dim3((NKV*HDIM)/BN,  T/BM), 256>>>(ph, wv_l, pv, nullptr, T, NKV*HDIM, DMODEL);
        qknorm_rope_k<<<T, NHEAD*HDIM>>>(pq, q_norm_w + (size_t)l*HDIM, position_ids, NHEAD);
        qknorm_rope_k<<<T, NKV*HDIM>>>(pk, k_norm_w + (size_t)l*HDIM, position_ids, NKV);
        attn_k<<<dim3(SEQ, NHEAD, BATCH), 128>>>();
        sgemm_nn<<<dim3(DMODEL/BN, T/BM), 256>>>(pao, wo_l, px, px, T, DMODEL, NHEAD*HDIM);

        // MoE block
        rmsnorm_k<<<T, 256>>>(px, ffn_norm_w + (size_t)l*DMODEL, ph);
        router_k<<<T, 256>>>(router_w + (size_t)l*DMODEL*NEXP);
        route_zero_k<<<1, 32>>>();
        route_count_k<<<(2*T)/256, 256>>>();
        route_prefix_k<<<1, 32>>>();
        route_assign_k<<<(2*T)/256, 256>>>();
        moe_gather_k<<<2*T, 256>>>();
        sgemm_moe<<<dim3(FDIM/BN, T/BM, NEXP), 256>>>(phg, gw_l, pgb, FDIM, DMODEL);
        sgemm_moe<<<dim3(FDIM/BN, T/BM, NEXP), 256>>>(phg, uw_l, pub, FDIM, DMODEL);
        moe_act_k<<<(2*T*FDIM)/256, 256>>>();
        sgemm_moe<<<dim3(DMODEL/BN, T/BM, NEXP), 256>>>(pgb, dw_l, pyb, DMODEL, FDIM);
        moe_combine_k<<<T, 256>>>();
    }

    // final norm + tied lm_head
    rmsnorm_k<<<T, 256>>>(px, final_norm_w, ph);
    sgemm_nt<<<dim3(VOCAB/BN, T/BM), 256>>>(ph, tok_emb, out, T, VOCAB, DMODEL);
}